// round 7
// baseline (speedup 1.0000x reference)
#include <cuda_runtime.h>
#include <cstdint>
#include <math.h>

// ============================================================================
// AttendAndSpell — single persistent kernel (1 graph node).
// 148 blocks x 256 threads, software grid barrier between phases.
// ============================================================================

#define B_   128
#define R_   512
#define HID_ 512
#define VOC_ 64
#define T_   128
#define NB   148
#define NT   256
#define NTH  (NB * NT)

// ---------------- scratch (static device allocations) ----------------
__device__ float g_hp  [(size_t)B_ * R_ * HID_];      // 134 MB
__device__ float g_phiT[HID_ * HID_];
__device__ float g_psiT[HID_ * HID_];
__device__ float g_W0T [1024 * 2048];                 // [w_ih0[:,64:]^T ; w_hh0^T]
__device__ float g_W1T [1024 * 2048];                 // [w_ih1^T ; w_hh1^T]
__device__ float g_outT[HID_ * VOC_];
__device__ float g_ohT [VOC_ * 2048];                 // ohT[v][n] = w_ih0[n][v]
__device__ float g_sq  [B_ * HID_];
__device__ float g_X0  [B_ * 1024];                   // [c | s0]
__device__ float g_X1  [B_ * 1024];                   // [s0 | s1]
__device__ float g_g0  [B_ * 2048];
__device__ float g_g1  [B_ * 2048];
__device__ float g_cs0 [B_ * HID_];
__device__ float g_cs1 [B_ * HID_];
__device__ int   g_z   [B_];
__device__ uint2 g_keys[T_];
__device__ float g_pm  [512];                         // attention partials (512 units)
__device__ float g_ps  [512];
__device__ float g_pv  [512 * 512];                   // 1 MB

__device__ unsigned g_bcnt = 0;
__device__ unsigned g_bgen = 0;

// ---------------- grid barrier (L2 atomics, L1 flushed by threadfence) ------
__device__ __forceinline__ void gbar() {
    __syncthreads();
    if (threadIdx.x == 0) {
        __threadfence();                                  // release + L1 inval
        unsigned gen = atomicAdd(&g_bgen, 0u);
        if (atomicAdd(&g_bcnt, 1u) == NB - 1u) {
            atomicExch(&g_bcnt, 0u);
            __threadfence();
            atomicAdd(&g_bgen, 1u);
        } else {
            while (atomicAdd(&g_bgen, 0u) == gen) { __nanosleep(64); }
        }
        __threadfence();                                  // acquire + L1 inval
    }
    __syncthreads();
}

// ---------------- Threefry-2x32 (bit-identical to the passing run) ----------
__device__ __forceinline__ void tf2x32(uint32_t k0, uint32_t k1,
                                       uint32_t x0, uint32_t x1,
                                       uint32_t& o0, uint32_t& o1) {
    uint32_t k2 = k0 ^ k1 ^ 0x1BD11BDAu;
    x0 += k0; x1 += k1;
#define RR(r) { x0 += x1; x1 = (x1 << (r)) | (x1 >> (32 - (r))); x1 ^= x0; }
    RR(13) RR(15) RR(26) RR(6)   x0 += k1; x1 += k2 + 1u;
    RR(17) RR(29) RR(16) RR(24)  x0 += k2; x1 += k0 + 2u;
    RR(13) RR(15) RR(26) RR(6)   x0 += k0; x1 += k1 + 3u;
    RR(17) RR(29) RR(16) RR(24)  x0 += k1; x1 += k2 + 4u;
    RR(13) RR(15) RR(26) RR(6)   x0 += k2; x1 += k0 + 5u;
#undef RR
    o0 = x0; o1 = x1;
}

__device__ __forceinline__ float bits_to_unit(uint32_t bits) {
    return __uint_as_float((bits >> 9) | 0x3f800000u) - 1.0f;
}

__device__ __forceinline__ float sigm(float x) { return 1.f / (1.f + expf(-x)); }

// ---------------- setup: transposes + state init + keys ---------------------
__device__ void phase_setup(const float* __restrict__ phi_w, const float* __restrict__ psi_w,
                            const float* __restrict__ w_ih0, const float* __restrict__ w_hh0,
                            const float* __restrict__ w_ih1, const float* __restrict__ w_hh1,
                            const float* __restrict__ out_w, const int* __restrict__ y) {
    int gt = blockIdx.x * NT + threadIdx.x;
    for (int i = gt; i < 512 * 512; i += NTH) {
        int k = i >> 9, j = i & 511;
        g_phiT[i] = phi_w[j * 512 + k];
        g_psiT[i] = psi_w[j * 512 + k];
    }
    for (int i = gt; i < 2048 * 512; i += NTH) {
        int k = i >> 11, n = i & 2047;
        g_W0T[i]               = w_ih0[n * 576 + 64 + k];
        g_W0T[512 * 2048 + i]  = w_hh0[n * 512 + k];
        g_W1T[i]               = w_ih1[n * 512 + k];
        g_W1T[512 * 2048 + i]  = w_hh1[n * 512 + k];
    }
    for (int i = gt; i < 64 * 2048; i += NTH) {
        int v = i >> 11, n = i & 2047;
        g_ohT[i] = w_ih0[n * 576 + v];
    }
    for (int i = gt; i < 512 * 64; i += NTH) {
        int k = i >> 6, v = i & 63;
        g_outT[i] = out_w[v * 512 + k];
    }
    for (int i = gt; i < B_ * 1024; i += NTH) { g_X0[i] = 0.f; g_X1[i] = 0.f; }
    for (int i = gt; i < B_ * HID_; i += NTH) { g_cs0[i] = 0.f; g_cs1[i] = 0.f; }
    if (gt < T_) {
        uint32_t a, b;
        tf2x32(0u, 42u, 0u, (uint32_t)gt, a, b);
        g_keys[gt] = make_uint2(a, b);
    }
    if (gt < B_) g_z[gt] = y[gt * (T_ + 1)];
}

// ---------------- 64x64 fp32 GEMM tile loop (4x4 micro) ---------------------
__device__ void gemm64(const float* __restrict__ A, int lda,
                       const float* __restrict__ Bm, int ldb,
                       float* __restrict__ C, int ldc,
                       const float* __restrict__ bias, int K, int Mt, int Nt) {
    __shared__ float As[16][68];
    __shared__ float Bs[16][64];
    int tid = threadIdx.x;
    int r   = tid >> 2;            // 0..63  (A row)
    int kc  = (tid & 3) << 2;      // 0,4,8,12
    int bkk = tid >> 4;            // 0..15  (B k)
    int bnc = (tid & 15) << 2;     // 0..60
    int tx  = tid & 15, ty = tid >> 4;
    int ntiles = Mt * Nt;
    for (int tile = blockIdx.x; tile < ntiles; tile += NB) {
        int m0 = (tile / Nt) << 6;
        int n0 = (tile % Nt) << 6;
        float acc[16];
#pragma unroll
        for (int i = 0; i < 16; i++) acc[i] = 0.f;
        const float* Ap = A + (size_t)(m0 + r) * lda + kc;
        const float* Bp = Bm + (size_t)bkk * ldb + n0 + bnc;
        for (int k0 = 0; k0 < K; k0 += 16) {
            float4 av = *(const float4*)(Ap + k0);
            float4 bv = *(const float4*)(Bp + (size_t)k0 * ldb);
            __syncthreads();
            As[kc][r] = av.x; As[kc + 1][r] = av.y;
            As[kc + 2][r] = av.z; As[kc + 3][r] = av.w;
            *(float4*)&Bs[bkk][bnc] = bv;
            __syncthreads();
#pragma unroll
            for (int kk = 0; kk < 16; kk++) {
                float4 a4 = *(const float4*)&As[kk][ty << 2];
                float4 b4 = *(const float4*)&Bs[kk][tx << 2];
                acc[0]  = fmaf(a4.x, b4.x, acc[0]);  acc[1]  = fmaf(a4.x, b4.y, acc[1]);
                acc[2]  = fmaf(a4.x, b4.z, acc[2]);  acc[3]  = fmaf(a4.x, b4.w, acc[3]);
                acc[4]  = fmaf(a4.y, b4.x, acc[4]);  acc[5]  = fmaf(a4.y, b4.y, acc[5]);
                acc[6]  = fmaf(a4.y, b4.z, acc[6]);  acc[7]  = fmaf(a4.y, b4.w, acc[7]);
                acc[8]  = fmaf(a4.z, b4.x, acc[8]);  acc[9]  = fmaf(a4.z, b4.y, acc[9]);
                acc[10] = fmaf(a4.z, b4.z, acc[10]); acc[11] = fmaf(a4.z, b4.w, acc[11]);
                acc[12] = fmaf(a4.w, b4.x, acc[12]); acc[13] = fmaf(a4.w, b4.y, acc[13]);
                acc[14] = fmaf(a4.w, b4.z, acc[14]); acc[15] = fmaf(a4.w, b4.w, acc[15]);
            }
        }
        float4 bb = make_float4(0.f, 0.f, 0.f, 0.f);
        if (bias) bb = *(const float4*)&bias[n0 + (tx << 2)];
#pragma unroll
        for (int i = 0; i < 4; i++) {
            float4 rr;
            rr.x = acc[i * 4 + 0] + bb.x; rr.y = acc[i * 4 + 1] + bb.y;
            rr.z = acc[i * 4 + 2] + bb.z; rr.w = acc[i * 4 + 3] + bb.w;
            *(float4*)&C[(size_t)(m0 + (ty << 2) + i) * ldc + n0 + (tx << 2)] = rr;
        }
    }
}

// ---------------- 32x64 fp32 GEMM tile loop (2x4 micro) ---------------------
__device__ void gemm32(const float* __restrict__ A, int lda,
                       const float* __restrict__ Bm, int ldb,
                       float* __restrict__ C, int ldc,
                       const float* __restrict__ bias, int K, int Mt, int Nt) {
    __shared__ float As2[16][34];
    __shared__ float Bs2[16][64];
    int tid = threadIdx.x;
    int tx = tid & 15, ty = tid >> 4;
    int ar = tid >> 3, akc = (tid & 7) << 1;
    int br = tid >> 4, bc = (tid & 15) << 2;
    int ntiles = Mt * Nt;
    for (int tile = blockIdx.x; tile < ntiles; tile += NB) {
        int m0 = (tile / Nt) << 5;
        int n0 = (tile % Nt) << 6;
        float acc[2][4] = {{0.f,0.f,0.f,0.f},{0.f,0.f,0.f,0.f}};
        const float* Ap = A + (size_t)(m0 + ar) * lda + akc;
        const float* Bp = Bm + (size_t)br * ldb + n0 + bc;
        for (int k0 = 0; k0 < K; k0 += 16) {
            float2 av = *(const float2*)(Ap + k0);
            float4 bv = *(const float4*)(Bp + (size_t)k0 * ldb);
            __syncthreads();
            As2[akc][ar] = av.x; As2[akc + 1][ar] = av.y;
            *(float4*)&Bs2[br][bc] = bv;
            __syncthreads();
#pragma unroll
            for (int kk = 0; kk < 16; kk++) {
                float a0 = As2[kk][ty * 2];
                float a1 = As2[kk][ty * 2 + 1];
                float4 b = *(const float4*)&Bs2[kk][tx << 2];
                acc[0][0] = fmaf(a0, b.x, acc[0][0]); acc[0][1] = fmaf(a0, b.y, acc[0][1]);
                acc[0][2] = fmaf(a0, b.z, acc[0][2]); acc[0][3] = fmaf(a0, b.w, acc[0][3]);
                acc[1][0] = fmaf(a1, b.x, acc[1][0]); acc[1][1] = fmaf(a1, b.y, acc[1][1]);
                acc[1][2] = fmaf(a1, b.z, acc[1][2]); acc[1][3] = fmaf(a1, b.w, acc[1][3]);
            }
        }
        float4 bb = make_float4(0.f, 0.f, 0.f, 0.f);
        if (bias) bb = *(const float4*)&bias[n0 + (tx << 2)];
#pragma unroll
        for (int i = 0; i < 2; i++) {
            float4 rr;
            rr.x = acc[i][0] + bb.x; rr.y = acc[i][1] + bb.y;
            rr.z = acc[i][2] + bb.z; rr.w = acc[i][3] + bb.w;
            *(float4*)&C[(size_t)(m0 + ty * 2 + i) * ldc + n0 + (tx << 2)] = rr;
        }
    }
}

// ---------------- attention partials: 512 units (b x 4 chunks of 128 rows) --
__device__ void attn_partial() {
    __shared__ float sv[8][512];
    __shared__ float sms[16];
    int tid = threadIdx.x, lane = tid & 31, w = tid >> 5;
    for (int u = blockIdx.x; u < 512; u += NB) {
        int b = u >> 2, ch = u & 3;
        const float* sqb = g_sq + b * HID_;
        float4 qf[4];
#pragma unroll
        for (int j = 0; j < 4; j++)
            qf[j] = *(const float4*)(sqb + j * 128 + lane * 4);
        float m = -INFINITY, s = 0.f;
        float4 ca[4];
#pragma unroll
        for (int j = 0; j < 4; j++) ca[j] = make_float4(0.f, 0.f, 0.f, 0.f);
        const float* hpb = g_hp + ((size_t)b * R_ + ch * 128) * HID_;
#pragma unroll 2
        for (int i = 0; i < 16; i++) {
            const float* row = hpb + (size_t)(w + i * 8) * HID_;
            float4 v[4];
#pragma unroll
            for (int j = 0; j < 4; j++)
                v[j] = *(const float4*)(row + j * 128 + lane * 4);
            float d = 0.f;
#pragma unroll
            for (int j = 0; j < 4; j++) {
                d = fmaf(qf[j].x, v[j].x, d); d = fmaf(qf[j].y, v[j].y, d);
                d = fmaf(qf[j].z, v[j].z, d); d = fmaf(qf[j].w, v[j].w, d);
            }
#pragma unroll
            for (int off = 16; off > 0; off >>= 1)
                d += __shfl_xor_sync(0xffffffffu, d, off);
            float mn = fmaxf(m, d);
            float corr = expf(m - mn);
            float p = expf(d - mn);
            s = s * corr + p;
#pragma unroll
            for (int j = 0; j < 4; j++) {
                ca[j].x = fmaf(p, v[j].x, ca[j].x * corr);
                ca[j].y = fmaf(p, v[j].y, ca[j].y * corr);
                ca[j].z = fmaf(p, v[j].z, ca[j].z * corr);
                ca[j].w = fmaf(p, v[j].w, ca[j].w * corr);
            }
            m = mn;
        }
#pragma unroll
        for (int j = 0; j < 4; j++)
            *(float4*)&sv[w][j * 128 + lane * 4] = ca[j];
        if (lane == 0) { sms[w] = m; sms[8 + w] = s; }
        __syncthreads();
        float M = sms[0];
#pragma unroll
        for (int i = 1; i < 8; i++) M = fmaxf(M, sms[i]);
        float we[8]; float S = 0.f;
#pragma unroll
        for (int i = 0; i < 8; i++) { we[i] = expf(sms[i] - M); S = fmaf(sms[8 + i], we[i], S); }
        for (int c = tid; c < 512; c += NT) {
            float a = 0.f;
#pragma unroll
            for (int i = 0; i < 8; i++) a = fmaf(we[i], sv[i][c], a);
            g_pv[(size_t)u * 512 + c] = a;
        }
        if (tid == 0) { g_pm[u] = M; g_ps[u] = S; }
        __syncthreads();
    }
}

// ---------------- attention combine: 128 blocks -> c into X0[:, :512] -------
__device__ void attn_combine() {
    int b = blockIdx.x;
    if (b >= B_) return;
    int tid = threadIdx.x;
    float m0 = g_pm[b * 4], m1 = g_pm[b * 4 + 1], m2 = g_pm[b * 4 + 2], m3 = g_pm[b * 4 + 3];
    float M = fmaxf(fmaxf(m0, m1), fmaxf(m2, m3));
    float w0 = expf(m0 - M), w1 = expf(m1 - M), w2 = expf(m2 - M), w3 = expf(m3 - M);
    float denom = g_ps[b * 4] * w0 + g_ps[b * 4 + 1] * w1
                + g_ps[b * 4 + 2] * w2 + g_ps[b * 4 + 3] * w3;
    float inv = 1.f / denom;
    const float* p0 = g_pv + (size_t)(b * 4 + 0) * 512;
    const float* p1 = g_pv + (size_t)(b * 4 + 1) * 512;
    const float* p2 = g_pv + (size_t)(b * 4 + 2) * 512;
    const float* p3 = g_pv + (size_t)(b * 4 + 3) * 512;
    for (int c = tid; c < 512; c += NT) {
        float a = w0 * p0[c] + w1 * p1[c] + w2 * p2[c] + w3 * p3[c];
        g_X0[(size_t)b * 1024 + c] = a * inv;
    }
}

// ---------------- LSTM pointwise phases -------------------------------------
__device__ void pw0(const float* __restrict__ b_ih, const float* __restrict__ b_hh) {
    for (int i = blockIdx.x * NT + threadIdx.x; i < B_ * HID_; i += NTH) {
        int b = i >> 9, d = i & 511;
        const float* gb = g_g0 + b * 2048;
        const float* oh = g_ohT + g_z[b] * 2048;
        float gi = gb[d]        + oh[d]        + b_ih[d]        + b_hh[d];
        float gf = gb[d + 512]  + oh[d + 512]  + b_ih[d + 512]  + b_hh[d + 512];
        float gg = gb[d + 1024] + oh[d + 1024] + b_ih[d + 1024] + b_hh[d + 1024];
        float go = gb[d + 1536] + oh[d + 1536] + b_ih[d + 1536] + b_hh[d + 1536];
        float ii = sigm(gi), ff = sigm(gf), g2 = tanhf(gg), oo = sigm(go);
        float c = ff * g_cs0[i] + ii * g2;
        g_cs0[i] = c;
        float hh = oo * tanhf(c);
        g_X0[b * 1024 + 512 + d] = hh;
        g_X1[b * 1024 + d]       = hh;
    }
}

__device__ void pw1(const float* __restrict__ b_ih, const float* __restrict__ b_hh) {
    for (int i = blockIdx.x * NT + threadIdx.x; i < B_ * HID_; i += NTH) {
        int b = i >> 9, d = i & 511;
        const float* gb = g_g1 + b * 2048;
        float gi = gb[d]        + b_ih[d]        + b_hh[d];
        float gf = gb[d + 512]  + b_ih[d + 512]  + b_hh[d + 512];
        float gg = gb[d + 1024] + b_ih[d + 1024] + b_hh[d + 1024];
        float go = gb[d + 1536] + b_ih[d + 1536] + b_hh[d + 1536];
        float ii = sigm(gi), ff = sigm(gf), g2 = tanhf(gg), oo = sigm(go);
        float c = ff * g_cs1[i] + ii * g2;
        g_cs1[i] = c;
        g_X1[b * 1024 + 512 + d] = oo * tanhf(c);
    }
}

// ---------------- logits + sampler (blocks 0..127) --------------------------
__device__ void logits_sample(int t, const float* __restrict__ out_b,
                              const int* __restrict__ y, float* __restrict__ out) {
    __shared__ float sl[4][64];
    __shared__ float sg2[64];
    int b = blockIdx.x;
    if (b < B_) {
        int tid = threadIdx.x, v = tid & 63, part = tid >> 6;
        const float* s1 = g_X1 + b * 1024 + 512 + part * 128;
        const float* ot = g_outT + part * 128 * 64 + v;
        float a0 = 0.f, a1 = 0.f;
#pragma unroll 4
        for (int k = 0; k < 128; k += 2) {
            a0 = fmaf(s1[k],     ot[k * 64],       a0);
            a1 = fmaf(s1[k + 1], ot[(k + 1) * 64], a1);
        }
        sl[part][v] = a0 + a1;
        __syncthreads();
        uint2 kt = g_keys[t];
        uint32_t k1a, k1b;
        tf2x32(kt.x, kt.y, 0u, 0u, k1a, k1b);
        if (tid < 64) {
            float logit = sl[0][tid] + sl[1][tid] + sl[2][tid] + sl[3][tid] + out_b[tid];
            out[((size_t)b * T_ + t) * VOC_ + tid] = logit;
            uint32_t r0, r1;
            tf2x32(k1a, k1b, 0u, (uint32_t)(b * VOC_ + tid), r0, r1);
            float f = bits_to_unit(r0 ^ r1);
            float u2 = fmaxf(f, 1.17549435e-38f);
            sg2[tid] = logit + (-logf(-logf(u2)));
        }
        __syncthreads();
        if (tid < 32) {
            float v0 = sg2[tid], v1 = sg2[tid + 32];
            int i0 = tid;
            if (v1 > v0) { v0 = v1; i0 = tid + 32; }
#pragma unroll
            for (int off = 16; off > 0; off >>= 1) {
                float ov = __shfl_down_sync(0xffffffffu, v0, off);
                int   oi = __shfl_down_sync(0xffffffffu, i0, off);
                if (ov > v0 || (ov == v0 && oi < i0)) { v0 = ov; i0 = oi; }
            }
            if (tid == 0) {
                uint32_t k2a, k2b, r0, r1;
                tf2x32(kt.x, kt.y, 0u, 1u, k2a, k2b);
                tf2x32(k2a, k2b, 0u, (uint32_t)b, r0, r1);
                float f = fmaxf(bits_to_unit(r0 ^ r1), 0.0f);
                g_z[b] = (f < 0.1f) ? i0 : y[b * (T_ + 1) + t + 1];
            }
        }
    }
    __syncthreads();
}

// ============================================================================
__global__ void __launch_bounds__(NT)
aas_persistent(const float* __restrict__ h,
               const float* __restrict__ phi_w, const float* __restrict__ phi_b,
               const float* __restrict__ psi_w, const float* __restrict__ psi_b,
               const float* __restrict__ w_ih0, const float* __restrict__ w_hh0,
               const float* __restrict__ b_ih0, const float* __restrict__ b_hh0,
               const float* __restrict__ w_ih1, const float* __restrict__ w_hh1,
               const float* __restrict__ b_ih1, const float* __restrict__ b_hh1,
               const float* __restrict__ out_w, const float* __restrict__ out_b,
               const int* __restrict__ y, float* __restrict__ out) {
    // setup: transposes + init
    phase_setup(phi_w, psi_w, w_ih0, w_hh0, w_ih1, w_hh1, out_w, y);
    gbar();
    // hp = h @ psi_w^T + psi_b   (65536 x 512, K=512)
    gemm64(h, 512, g_psiT, 512, g_hp, 512, psi_b, 512, 1024, 8);
    gbar();
    // initial sq (s1 = 0 -> sq = phi_b, via the same GEMM path)
    gemm32(g_X1 + 512, 1024, g_phiT, 512, g_sq, 512, phi_b, 512, 4, 8);
    gbar();

    for (int t = 0; t < T_; t++) {
        attn_partial();                                              gbar();
        attn_combine();                                              gbar();
        gemm32(g_X0, 1024, g_W0T, 2048, g_g0, 2048, nullptr, 1024, 4, 32); gbar();
        pw0(b_ih0, b_hh0);                                           gbar();
        gemm32(g_X1, 1024, g_W1T, 2048, g_g1, 2048, nullptr, 1024, 4, 32); gbar();
        pw1(b_ih1, b_hh1);                                           gbar();
        // logits + sample for this step, plus sq for the next step (fused phase)
        logits_sample(t, out_b, y, out);
        gemm32(g_X1 + 512, 1024, g_phiT, 512, g_sq, 512, phi_b, 512, 4, 8);
        gbar();
    }
}

extern "C" void kernel_launch(void* const* d_in, const int* in_sizes, int n_in,
                              void* d_out, int out_size) {
    const float* h     = (const float*)d_in[0];
    const float* phi_w = (const float*)d_in[1];
    const float* phi_b = (const float*)d_in[2];
    const float* psi_w = (const float*)d_in[3];
    const float* psi_b = (const float*)d_in[4];
    const float* w_ih0 = (const float*)d_in[5];
    const float* w_hh0 = (const float*)d_in[6];
    const float* b_ih0 = (const float*)d_in[7];
    const float* b_hh0 = (const float*)d_in[8];
    const float* w_ih1 = (const float*)d_in[9];
    const float* w_hh1 = (const float*)d_in[10];
    const float* b_ih1 = (const float*)d_in[11];
    const float* b_hh1 = (const float*)d_in[12];
    const float* out_w = (const float*)d_in[13];
    const float* out_b = (const float*)d_in[14];
    const int*   y     = (const int*)d_in[15];
    float* out = (float*)d_out;

    aas_persistent<<<NB, NT>>>(h, phi_w, phi_b, psi_w, psi_b,
                               w_ih0, w_hh0, b_ih0, b_hh0,
                               w_ih1, w_hh1, b_ih1, b_hh1,
                               out_w, out_b, y, out);
}